// round 9
// baseline (speedup 1.0000x reference)
#include <cuda_runtime.h>
#include <cuda_fp16.h>
#include <cstdint>
#include <cstddef>

#define BATCH 4
#define SEQ   2048
#define DIM   1024
#define MTOT  (BATCH * SEQ)   // 8192

// lo-residual arrays are stored pre-scaled by LSCALE to keep fp16 products
// out of the subnormal range (f16-accumulator MMAs would flush them).
#define LSCALE 2048.0f
#define ILSCALE (1.0f / 2048.0f)

// ---- GEMM tiling ----
#define BM 128
#define BN 128
#define BK 32                 // 32 halves per row per tile
#define RSB 80                // smem row stride bytes (32*2 + 16 pad)
#define TILE_BYTES (128 * RSB)          // 10240 per (array) tile
#define OFF_AH 0
#define OFF_AL (TILE_BYTES)
#define OFF_BH (2 * TILE_BYTES)
#define OFF_BL (3 * TILE_BYTES)
#define STAGE (4 * TILE_BYTES)          // 40960
#define NSTAGE 3
#define SMEM_REQ (NSTAGE * STAGE)       // 122880

#define NTHR 512              // 16 warps: 4x4 warp grid, 32x32 warp tile

// ---- device scratch ----
__device__ __half g_xh[(size_t)MTOT * DIM];
__device__ __half g_xl[(size_t)MTOT * DIM];
__device__ __half g_wqh[(size_t)DIM * DIM];
__device__ __half g_wql[(size_t)DIM * DIM];
__device__ __half g_wkh[(size_t)DIM * DIM];
__device__ __half g_wkl[(size_t)DIM * DIM];
__device__ __half g_wvh[(size_t)DIM * DIM];
__device__ __half g_wvl[(size_t)DIM * DIM];
__device__ __half g_Qh[(size_t)MTOT * DIM];
__device__ __half g_Ql[(size_t)MTOT * DIM];
__device__ __half g_Kh[(size_t)MTOT * DIM];
__device__ __half g_Kl[(size_t)MTOT * DIM];
__device__ __half g_Vth[(size_t)MTOT * DIM];   // [b][v][s] transposed V
__device__ __half g_Vtl[(size_t)MTOT * DIM];
__device__ float  g_S [(size_t)BATCH * SEQ * SEQ];
__device__ __half g_Ph[(size_t)BATCH * SEQ * SEQ];

struct ProjArgs {
    const __half* bh[3];
    const __half* bl[3];
    const float*  bias[3];
    __half* oh[3];
    __half* ol[3];
};

// ---------------------------------------------------------------------------
__device__ __forceinline__ uint32_t cvta_smem(const void* p) {
    uint32_t r;
    asm("{ .reg .u64 t; cvta.to.shared.u64 t, %1; cvt.u32.u64 %0, t; }"
        : "=r"(r) : "l"(p));
    return r;
}
__device__ __forceinline__ void cpa16(uint32_t d, const void* s) {
    asm volatile("cp.async.cg.shared.global [%0], [%1], 16;" :: "r"(d), "l"(s));
}
__device__ __forceinline__ void cp_commit() {
    asm volatile("cp.async.commit_group;" ::: "memory");
}
__device__ __forceinline__ void ldsm4(uint32_t& r0, uint32_t& r1, uint32_t& r2,
                                      uint32_t& r3, uint32_t addr) {
    asm volatile("ldmatrix.sync.aligned.m8n8.x4.shared.b16 {%0,%1,%2,%3}, [%4];"
                 : "=r"(r0), "=r"(r1), "=r"(r2), "=r"(r3) : "r"(addr));
}
// main term: fp32 accumulate
__device__ __forceinline__ void mma16816(float* c, const uint32_t* a,
                                         const uint32_t* b) {
    asm volatile(
        "mma.sync.aligned.m16n8k16.row.col.f32.f16.f16.f32 "
        "{%0,%1,%2,%3}, {%4,%5,%6,%7}, {%8,%9}, {%0,%1,%2,%3};"
        : "+f"(c[0]), "+f"(c[1]), "+f"(c[2]), "+f"(c[3])
        : "r"(a[0]), "r"(a[1]), "r"(a[2]), "r"(a[3]), "r"(b[0]), "r"(b[1]));
}
// correction terms: fp16 accumulate (values are small, pre-scaled by LSCALE)
__device__ __forceinline__ void mma16816h(uint32_t* c, const uint32_t* a,
                                          const uint32_t* b) {
    asm volatile(
        "mma.sync.aligned.m16n8k16.row.col.f16.f16.f16.f16 "
        "{%0,%1}, {%2,%3,%4,%5}, {%6,%7}, {%0,%1};"
        : "+r"(c[0]), "+r"(c[1])
        : "r"(a[0]), "r"(a[1]), "r"(a[2]), "r"(a[3]), "r"(b[0]), "r"(b[1]));
}

// ---------------------------------------------------------------------------
// Split-fp16 GEMM:  C = A @ B^T  (A:[M,K], B:[N,K], K-major), main fp32-accum
// + (Ah·Bl' [+ Al'·Bh]) fp16-accum corrections, lo arrays pre-scaled LSCALE.
// 512 threads, 16 warps in 4x4 grid, 32x32 warp tile.
// EPI 0: plain fp32 out (scores / final out)
// EPI 3: fused QKV projection — blockIdx.z picks W/bias/output; z==2 writes
//        transposed split (Vt), z<2 writes row-major split (Q/K).
// TERMS 3: Ah·Bh + Ah·Bl + Al·Bh ;  TERMS 2: Ah·Bh + Ah·Bl (no A-lo at all)
// ---------------------------------------------------------------------------
template <int EPI, int TERMS>
__global__ __launch_bounds__(NTHR, 1)
void hgemm_kernel(const __half* __restrict__ Ahg, const __half* __restrict__ Alg,
                  const __half* __restrict__ Bhg, const __half* __restrict__ Blg,
                  float* __restrict__ C0, ProjArgs pa,
                  int N, int K,
                  long long sA, long long sB, long long sC)
{
    extern __shared__ char smem_raw[];
    const uint32_t sb = cvta_smem(smem_raw);

    const int tid  = threadIdx.x;
    const int wid  = tid >> 5;
    const int lane = tid & 31;
    const long long bz = blockIdx.z;

    const __half* Bh_;
    const __half* Bl_;
    if (EPI == 3) { Bh_ = pa.bh[bz]; Bl_ = pa.bl[bz]; }
    else          { Bh_ = Bhg + bz * sB; Bl_ = Blg + bz * sB; }
    const __half* Ah_ = Ahg + (EPI == 3 ? 0 : bz * sA);
    const __half* Al_ = (TERMS == 3) ? (Alg + (EPI == 3 ? 0 : bz * sA)) : nullptr;

    const int m0 = blockIdx.y * BM;
    const int n0 = blockIdx.x * BN;

    const int wm = (wid & 3) * 32;   // warp row offset (4 warps in m)
    const int wn = (wid >> 2) * 32;  // warp col offset (4 warps in n)

    float c[2][4][4];
    uint32_t cc[2][4][2];            // f16x2 correction accumulators
#pragma unroll
    for (int mt = 0; mt < 2; ++mt)
#pragma unroll
        for (int nt = 0; nt < 4; ++nt) {
#pragma unroll
            for (int i = 0; i < 4; ++i) c[mt][nt][i] = 0.f;
            cc[mt][nt][0] = 0u; cc[mt][nt][1] = 0u;
        }

    const int NK = K / BK;

    // loader: 512 threads, one 16B chunk per array; row=tid>>2, chunk=(tid&3)
    const int lrow = tid >> 2;
    const int lkcc = (tid & 3) * 8;
    const uint32_t lso = (uint32_t)(lrow * RSB + lkcc * 2);

    auto load_stage = [&](int slot, int kc) {
        const uint32_t tb = sb + slot * STAGE;
        const long long ga = (long long)(m0 + lrow) * K + kc + lkcc;
        const long long gb = (long long)(n0 + lrow) * K + kc + lkcc;
        cpa16(tb + OFF_AH + lso, Ah_ + ga);
        if (TERMS == 3) cpa16(tb + OFF_AL + lso, Al_ + ga);
        cpa16(tb + OFF_BH + lso, Bh_ + gb);
        cpa16(tb + OFF_BL + lso, Bl_ + gb);
    };

    // prefetch NSTAGE-1 stages
#pragma unroll
    for (int s = 0; s < NSTAGE - 1; ++s) { load_stage(s, s * BK); cp_commit(); }

    const int a_row = (lane & 15);
    const int a_kof = (lane >> 4) * 8;
    const int b_row = ((lane >> 4) << 3) + (lane & 7);
    const int b_kof = ((lane >> 3) & 1) * 8;

    for (int it = 0; it < NK; ++it) {
        if (it + NSTAGE - 1 < NK)
            load_stage((it + NSTAGE - 1) % NSTAGE, (it + NSTAGE - 1) * BK);
        cp_commit();
        asm volatile("cp.async.wait_group 2;" ::: "memory");
        __syncthreads();

        const uint32_t tb = sb + (it % NSTAGE) * STAGE;
#pragma unroll
        for (int ks = 0; ks < 2; ++ks) {
            const int kh = ks * 16;
            uint32_t ah[2][4], al[2][4], bh[4][2], bl[4][2];
#pragma unroll
            for (int mt = 0; mt < 2; ++mt) {
                const uint32_t ao = (uint32_t)((wm + mt * 16 + a_row) * RSB
                                               + (kh + a_kof) * 2);
                ldsm4(ah[mt][0], ah[mt][1], ah[mt][2], ah[mt][3], tb + OFF_AH + ao);
                if (TERMS == 3)
                    ldsm4(al[mt][0], al[mt][1], al[mt][2], al[mt][3], tb + OFF_AL + ao);
            }
#pragma unroll
            for (int ng = 0; ng < 2; ++ng) {
                const uint32_t bo = (uint32_t)((wn + ng * 16 + b_row) * RSB
                                               + (kh + b_kof) * 2);
                ldsm4(bh[ng*2][0], bh[ng*2][1], bh[ng*2+1][0], bh[ng*2+1][1],
                      tb + OFF_BH + bo);
                ldsm4(bl[ng*2][0], bl[ng*2][1], bl[ng*2+1][0], bl[ng*2+1][1],
                      tb + OFF_BL + bo);
            }
#pragma unroll
            for (int mt = 0; mt < 2; ++mt)
#pragma unroll
                for (int nt = 0; nt < 4; ++nt) {
                    mma16816(c[mt][nt], ah[mt], bh[nt]);
                    mma16816h(cc[mt][nt], ah[mt], bl[nt]);
                    if (TERMS == 3) mma16816h(cc[mt][nt], al[mt], bh[nt]);
                }
        }
        __syncthreads();
    }

    // ---- epilogue ----
    const int mrow = lane >> 2;
    const int ncol = (lane & 3) * 2;
    const float* bias = (EPI == 3) ? pa.bias[bz] : nullptr;

#pragma unroll
    for (int mt = 0; mt < 2; ++mt)
#pragma unroll
        for (int nt = 0; nt < 4; ++nt) {
            __half2 p0 = *(__half2*)&cc[mt][nt][0];
            __half2 p1 = *(__half2*)&cc[mt][nt][1];
            float corr[4] = { __low2float(p0), __high2float(p0),
                              __low2float(p1), __high2float(p1) };
#pragma unroll
            for (int hf = 0; hf < 2; ++hf) {
                const int m = m0 + wm + mt * 16 + mrow + hf * 8;
                const int n = n0 + wn + nt * 8 + ncol;
                float v0 = c[mt][nt][hf * 2 + 0] + corr[hf * 2 + 0] * ILSCALE;
                float v1 = c[mt][nt][hf * 2 + 1] + corr[hf * 2 + 1] * ILSCALE;

                if (EPI == 0) {
                    float2 v; v.x = v0; v.y = v1;
                    *(float2*)&C0[bz * sC + (size_t)m * N + n] = v;
                } else {
                    v0 += bias[n]; v1 += bias[n + 1];
                    __half h0 = __float2half_rn(v0);
                    __half h1 = __float2half_rn(v1);
                    __half l0 = __float2half_rn((v0 - __half2float(h0)) * LSCALE);
                    __half l1 = __float2half_rn((v1 - __half2float(h1)) * LSCALE);
                    if (bz < 2) {
                        __half2 hh; hh.x = h0; hh.y = h1;
                        __half2 ll; ll.x = l0; ll.y = l1;
                        *(__half2*)&pa.oh[bz][(size_t)m * N + n] = hh;
                        *(__half2*)&pa.ol[bz][(size_t)m * N + n] = ll;
                    } else {
                        const int b = m >> 11;          // SEQ = 2048
                        const int s = m & 2047;
                        const size_t base = (size_t)b * DIM * SEQ + s;
                        pa.oh[2][base + (size_t)n * SEQ]       = h0;
                        pa.oh[2][base + (size_t)(n + 1) * SEQ] = h1;
                        pa.ol[2][base + (size_t)n * SEQ]       = l0;
                        pa.ol[2][base + (size_t)(n + 1) * SEQ] = l1;
                    }
                }
            }
        }
}

// ---------------------------------------------------------------------------
// fp32 -> fp16 hi + scaled-lo split (x)
// ---------------------------------------------------------------------------
__global__ __launch_bounds__(256)
void split_kernel(const float* __restrict__ in, __half* __restrict__ hi,
                  __half* __restrict__ lo, int n4)
{
    int i = blockIdx.x * 256 + threadIdx.x;
    if (i < n4) {
        float4 v = ((const float4*)in)[i];
        __half h[4], l[4];
        float vv[4] = {v.x, v.y, v.z, v.w};
#pragma unroll
        for (int j = 0; j < 4; ++j) {
            h[j] = __float2half_rn(vv[j]);
            l[j] = __float2half_rn((vv[j] - __half2float(h[j])) * LSCALE);
        }
        ((uint2*)hi)[i] = *(uint2*)h;
        ((uint2*)lo)[i] = *(uint2*)l;
    }
}

// fused W splits: z picks which weight matrix
__global__ __launch_bounds__(256)
void wsplit_kernel(const float* __restrict__ s0, const float* __restrict__ s1,
                   const float* __restrict__ s2,
                   __half* __restrict__ h0, __half* __restrict__ l0,
                   __half* __restrict__ h1, __half* __restrict__ l1,
                   __half* __restrict__ h2, __half* __restrict__ l2, int n4)
{
    const int z = blockIdx.z;
    const float* in = z == 0 ? s0 : z == 1 ? s1 : s2;
    __half* hi = z == 0 ? h0 : z == 1 ? h1 : h2;
    __half* lo = z == 0 ? l0 : z == 1 ? l1 : l2;
    int i = blockIdx.x * 256 + threadIdx.x;
    if (i < n4) {
        float4 v = ((const float4*)in)[i];
        __half h[4], l[4];
        float vv[4] = {v.x, v.y, v.z, v.w};
#pragma unroll
        for (int j = 0; j < 4; ++j) {
            h[j] = __float2half_rn(vv[j]);
            l[j] = __float2half_rn((vv[j] - __half2float(h[j])) * LSCALE);
        }
        ((uint2*)hi)[i] = *(uint2*)h;
        ((uint2*)lo)[i] = *(uint2*)l;
    }
}

// ---------------------------------------------------------------------------
// Row softmax over 2048, post-scale by norm, fp16 hi output only
// ---------------------------------------------------------------------------
__global__ __launch_bounds__(256)
void softmax_kernel(const float* __restrict__ S, __half* __restrict__ Ph,
                    float norm)
{
    const float* p = S + (long long)blockIdx.x * SEQ;
    __half* ph = Ph + (long long)blockIdx.x * SEQ;
    const int t = threadIdx.x;
    __shared__ float red[8];

    float v[8];
    float mx = -1e30f;
#pragma unroll
    for (int i = 0; i < 8; ++i) {
        v[i] = p[t + (i << 8)];
        mx = fmaxf(mx, v[i]);
    }
#pragma unroll
    for (int o = 16; o; o >>= 1) mx = fmaxf(mx, __shfl_xor_sync(0xffffffffu, mx, o));
    if ((t & 31) == 0) red[t >> 5] = mx;
    __syncthreads();
    mx = red[0];
#pragma unroll
    for (int i = 1; i < 8; ++i) mx = fmaxf(mx, red[i]);

    float s = 0.f;
#pragma unroll
    for (int i = 0; i < 8; ++i) { v[i] = __expf(v[i] - mx); s += v[i]; }
#pragma unroll
    for (int o = 16; o; o >>= 1) s += __shfl_xor_sync(0xffffffffu, s, o);
    __syncthreads();
    if ((t & 31) == 0) red[t >> 5] = s;
    __syncthreads();
    s = 0.f;
#pragma unroll
    for (int i = 0; i < 8; ++i) s += red[i];

    const float inv = norm / s;
#pragma unroll
    for (int i = 0; i < 8; ++i)
        ph[t + (i << 8)] = __float2half_rn(v[i] * inv);
}

// ---------------------------------------------------------------------------
extern "C" void kernel_launch(void* const* d_in, const int* in_sizes, int n_in,
                              void* d_out, int out_size)
{
    (void)in_sizes; (void)n_in; (void)out_size;
    const float* x  = (const float*)d_in[0];
    const float* Wq = (const float*)d_in[1];
    const float* bq = (const float*)d_in[2];
    const float* Wk = (const float*)d_in[3];
    const float* bk = (const float*)d_in[4];
    const float* Wv = (const float*)d_in[5];
    const float* bv = (const float*)d_in[6];
    float* out = (float*)d_out;

    __half *xh, *xl, *wqh, *wql, *wkh, *wkl, *wvh, *wvl;
    __half *Qh, *Ql, *Kh, *Kl, *Vth, *Vtl, *Ph;
    float *S;
    cudaGetSymbolAddress((void**)&xh,  g_xh);  cudaGetSymbolAddress((void**)&xl,  g_xl);
    cudaGetSymbolAddress((void**)&wqh, g_wqh); cudaGetSymbolAddress((void**)&wql, g_wql);
    cudaGetSymbolAddress((void**)&wkh, g_wkh); cudaGetSymbolAddress((void**)&wkl, g_wkl);
    cudaGetSymbolAddress((void**)&wvh, g_wvh); cudaGetSymbolAddress((void**)&wvl, g_wvl);
    cudaGetSymbolAddress((void**)&Qh,  g_Qh);  cudaGetSymbolAddress((void**)&Ql,  g_Ql);
    cudaGetSymbolAddress((void**)&Kh,  g_Kh);  cudaGetSymbolAddress((void**)&Kl,  g_Kl);
    cudaGetSymbolAddress((void**)&Vth, g_Vth); cudaGetSymbolAddress((void**)&Vtl, g_Vtl);
    cudaGetSymbolAddress((void**)&S,   g_S);
    cudaGetSymbolAddress((void**)&Ph,  g_Ph);

    cudaFuncSetAttribute(hgemm_kernel<0,3>, cudaFuncAttributeMaxDynamicSharedMemorySize, SMEM_REQ);
    cudaFuncSetAttribute(hgemm_kernel<0,2>, cudaFuncAttributeMaxDynamicSharedMemorySize, SMEM_REQ);
    cudaFuncSetAttribute(hgemm_kernel<3,3>, cudaFuncAttributeMaxDynamicSharedMemorySize, SMEM_REQ);

    const dim3 blk(256);
    const dim3 gblk(NTHR);
    ProjArgs pa;
    pa.bh[0] = wqh; pa.bh[1] = wkh; pa.bh[2] = wvh;
    pa.bl[0] = wql; pa.bl[1] = wkl; pa.bl[2] = wvl;
    pa.bias[0] = bq; pa.bias[1] = bk; pa.bias[2] = bv;
    pa.oh[0] = Qh; pa.oh[1] = Kh; pa.oh[2] = Vth;
    pa.ol[0] = Ql; pa.ol[1] = Kl; pa.ol[2] = Vtl;
    ProjArgs pz{};   // unused for non-projection GEMMs

    // 0: split x
    split_kernel<<<MTOT * DIM / 4 / 256, blk>>>(x, xh, xl, MTOT * DIM / 4);
    // 1: split all three weight matrices (fused via z)
    wsplit_kernel<<<dim3(DIM * DIM / 4 / 256, 1, 3), blk>>>(
        Wq, Wk, Wv, wqh, wql, wkh, wkl, wvh, wvl, DIM * DIM / 4);

    // 2: fused QKV projections: z in {Q, K, V}
    hgemm_kernel<3,3><<<dim3(DIM / BN, MTOT / BM, 3), gblk, SMEM_REQ>>>(
        xh, xl, nullptr, nullptr, nullptr, pa, DIM, DIM, 0, 0, 0);

    // 3: scores = Q @ K^T per batch
    hgemm_kernel<0,3><<<dim3(SEQ / BN, SEQ / BM, BATCH), gblk, SMEM_REQ>>>(
        Qh, Ql, Kh, Kl, S, pz, SEQ, DIM,
        (long long)SEQ * DIM, (long long)SEQ * DIM, (long long)SEQ * SEQ);

    // 4: softmax + post-scale 1/32
    softmax_kernel<<<BATCH * SEQ, blk>>>(S, Ph, 0.03125f);

    // 5: out = P @ Vt^T per batch (2-term: Ph·Vh + Ph·Vl)
    hgemm_kernel<0,2><<<dim3(DIM / BN, SEQ / BM, BATCH), gblk, SMEM_REQ>>>(
        Ph, nullptr, Vth, Vtl, out, pz, DIM, SEQ,
        (long long)SEQ * SEQ, (long long)DIM * SEQ, (long long)SEQ * DIM);
}

// round 10
// speedup vs baseline: 1.1586x; 1.1586x over previous
#include <cuda_runtime.h>
#include <cuda_fp16.h>
#include <cstdint>
#include <cstddef>

#define BATCH 4
#define SEQ   2048
#define DIM   1024
#define MTOT  (BATCH * SEQ)   // 8192

// lo-residual arrays are stored pre-scaled by LSCALE to keep fp16 products
// out of the subnormal range (f16-accumulator MMAs would flush them).
#define LSCALE 2048.0f
#define ILSCALE (1.0f / 2048.0f)

// ---- GEMM tiling ----
#define BM 128
#define BN 64
#define BK 32                 // 32 halves per row per tile
#define RSB 80                // smem row stride bytes (32*2 + 16 pad)
#define A_TILE (BM * RSB)     // 10240
#define B_TILE (BN * RSB)     // 5120
#define OFF_AH 0
#define OFF_AL (A_TILE)
#define OFF_BH (2 * A_TILE)
#define OFF_BL (2 * A_TILE + B_TILE)
#define STAGE (2 * A_TILE + 2 * B_TILE)  // 30720
#define NSTAGE 3
#define SMEM_REQ (NSTAGE * STAGE)        // 92160 -> 2 CTAs/SM fit in 228KB

#define NTHR 256              // 8 warps: 4x2 warp grid, 32x32 warp tile

// ---- device scratch ----
__device__ __half g_xh[(size_t)MTOT * DIM];
__device__ __half g_xl[(size_t)MTOT * DIM];
__device__ __half g_wqh[(size_t)DIM * DIM];
__device__ __half g_wql[(size_t)DIM * DIM];
__device__ __half g_wkh[(size_t)DIM * DIM];
__device__ __half g_wkl[(size_t)DIM * DIM];
__device__ __half g_wvh[(size_t)DIM * DIM];
__device__ __half g_wvl[(size_t)DIM * DIM];
__device__ __half g_Qh[(size_t)MTOT * DIM];
__device__ __half g_Ql[(size_t)MTOT * DIM];
__device__ __half g_Kh[(size_t)MTOT * DIM];
__device__ __half g_Kl[(size_t)MTOT * DIM];
__device__ __half g_Vth[(size_t)MTOT * DIM];   // [b][v][s] transposed V
__device__ __half g_Vtl[(size_t)MTOT * DIM];
__device__ float  g_S [(size_t)BATCH * SEQ * SEQ];
__device__ __half g_Ph[(size_t)BATCH * SEQ * SEQ];

struct ProjArgs {
    const __half* bh[3];
    const __half* bl[3];
    const float*  bias[3];
    __half* oh[3];
    __half* ol[3];
};

// ---------------------------------------------------------------------------
__device__ __forceinline__ uint32_t cvta_smem(const void* p) {
    uint32_t r;
    asm("{ .reg .u64 t; cvta.to.shared.u64 t, %1; cvt.u32.u64 %0, t; }"
        : "=r"(r) : "l"(p));
    return r;
}
__device__ __forceinline__ void cpa16(uint32_t d, const void* s) {
    asm volatile("cp.async.cg.shared.global [%0], [%1], 16;" :: "r"(d), "l"(s));
}
__device__ __forceinline__ void cp_commit() {
    asm volatile("cp.async.commit_group;" ::: "memory");
}
__device__ __forceinline__ void ldsm4(uint32_t& r0, uint32_t& r1, uint32_t& r2,
                                      uint32_t& r3, uint32_t addr) {
    asm volatile("ldmatrix.sync.aligned.m8n8.x4.shared.b16 {%0,%1,%2,%3}, [%4];"
                 : "=r"(r0), "=r"(r1), "=r"(r2), "=r"(r3) : "r"(addr));
}
// main term: fp32 accumulate
__device__ __forceinline__ void mma16816(float* c, const uint32_t* a,
                                         const uint32_t* b) {
    asm volatile(
        "mma.sync.aligned.m16n8k16.row.col.f32.f16.f16.f32 "
        "{%0,%1,%2,%3}, {%4,%5,%6,%7}, {%8,%9}, {%0,%1,%2,%3};"
        : "+f"(c[0]), "+f"(c[1]), "+f"(c[2]), "+f"(c[3])
        : "r"(a[0]), "r"(a[1]), "r"(a[2]), "r"(a[3]), "r"(b[0]), "r"(b[1]));
}
// correction terms: fp16 accumulate (values are small, pre-scaled by LSCALE)
__device__ __forceinline__ void mma16816h(uint32_t* c, const uint32_t* a,
                                          const uint32_t* b) {
    asm volatile(
        "mma.sync.aligned.m16n8k16.row.col.f16.f16.f16.f16 "
        "{%0,%1}, {%2,%3,%4,%5}, {%6,%7}, {%0,%1};"
        : "+r"(c[0]), "+r"(c[1])
        : "r"(a[0]), "r"(a[1]), "r"(a[2]), "r"(a[3]), "r"(b[0]), "r"(b[1]));
}

// ---------------------------------------------------------------------------
// Split-fp16 GEMM:  C = A @ B^T  (A:[M,K], B:[N,K], K-major), main fp32-accum
// + (Ah·Bl' [+ Al'·Bh]) fp16-accum corrections, lo arrays pre-scaled LSCALE.
// 128x64 CTA tile, 256 threads, 8 warps (4x2), 32x32 warp tile.
// 2 CTAs/SM (launch_bounds minBlocks=2) so barrier phases de-correlate and
// one CTA's LDSM burst overlaps the other CTA's HMMA burst.
// EPI 0: plain fp32 out; EPI 3: fused QKV projection (z picks W/bias/out,
//        z==2 writes transposed split Vt).
// TERMS 3: Ah·Bh + Ah·Bl + Al·Bh ;  TERMS 2: Ah·Bh + Ah·Bl
// ---------------------------------------------------------------------------
template <int EPI, int TERMS>
__global__ __launch_bounds__(NTHR, 2)
void hgemm_kernel(const __half* __restrict__ Ahg, const __half* __restrict__ Alg,
                  const __half* __restrict__ Bhg, const __half* __restrict__ Blg,
                  float* __restrict__ C0, ProjArgs pa,
                  int N, int K,
                  long long sA, long long sB, long long sC)
{
    extern __shared__ char smem_raw[];
    const uint32_t sb = cvta_smem(smem_raw);

    const int tid  = threadIdx.x;
    const int wid  = tid >> 5;
    const int lane = tid & 31;
    const long long bz = blockIdx.z;

    const __half* Bh_;
    const __half* Bl_;
    if (EPI == 3) { Bh_ = pa.bh[bz]; Bl_ = pa.bl[bz]; }
    else          { Bh_ = Bhg + bz * sB; Bl_ = Blg + bz * sB; }
    const __half* Ah_ = Ahg + (EPI == 3 ? 0 : bz * sA);
    const __half* Al_ = (TERMS == 3) ? (Alg + (EPI == 3 ? 0 : bz * sA)) : nullptr;

    const int m0 = blockIdx.y * BM;
    const int n0 = blockIdx.x * BN;

    const int wm = (wid & 3) * 32;   // warp row offset (4 warps in m)
    const int wn = (wid >> 2) * 32;  // warp col offset (2 warps in n)

    float c[2][4][4];
    uint32_t cc[2][4][2];            // f16x2 correction accumulators
#pragma unroll
    for (int mt = 0; mt < 2; ++mt)
#pragma unroll
        for (int nt = 0; nt < 4; ++nt) {
#pragma unroll
            for (int i = 0; i < 4; ++i) c[mt][nt][i] = 0.f;
            cc[mt][nt][0] = 0u; cc[mt][nt][1] = 0u;
        }

    const int NK = K / BK;

    // loader: A tile = 512 16B chunks (2 rounds of 256), B tile = 256 chunks
    const int arow = tid >> 2;            // A round r: row = arow + r*64
    const int akcc = (tid & 3) * 8;
    const int brow = tid >> 2;            // B: rows 0..63
    const uint32_t aso = (uint32_t)(arow * RSB + akcc * 2);
    const uint32_t bso = (uint32_t)(brow * RSB + akcc * 2);

    auto load_stage = [&](int slot, int kc) {
        const uint32_t tb = sb + slot * STAGE;
#pragma unroll
        for (int r = 0; r < 2; ++r) {
            const long long ga = (long long)(m0 + arow + r * 64) * K + kc + akcc;
            const uint32_t so = aso + (uint32_t)(r * 64 * RSB);
            cpa16(tb + OFF_AH + so, Ah_ + ga);
            if (TERMS == 3) cpa16(tb + OFF_AL + so, Al_ + ga);
        }
        const long long gb = (long long)(n0 + brow) * K + kc + akcc;
        cpa16(tb + OFF_BH + bso, Bh_ + gb);
        cpa16(tb + OFF_BL + bso, Bl_ + gb);
    };

    // prefetch NSTAGE-1 stages
#pragma unroll
    for (int s = 0; s < NSTAGE - 1; ++s) { load_stage(s, s * BK); cp_commit(); }

    const int a_row = (lane & 15);
    const int a_kof = (lane >> 4) * 8;
    const int b_row = ((lane >> 4) << 3) + (lane & 7);
    const int b_kof = ((lane >> 3) & 1) * 8;

    for (int it = 0; it < NK; ++it) {
        if (it + NSTAGE - 1 < NK)
            load_stage((it + NSTAGE - 1) % NSTAGE, (it + NSTAGE - 1) * BK);
        cp_commit();
        asm volatile("cp.async.wait_group 2;" ::: "memory");
        __syncthreads();

        const uint32_t tb = sb + (it % NSTAGE) * STAGE;
#pragma unroll
        for (int ks = 0; ks < 2; ++ks) {
            const int kh = ks * 16;
            uint32_t ah[2][4], al[2][4], bh[4][2], bl[4][2];
#pragma unroll
            for (int mt = 0; mt < 2; ++mt) {
                const uint32_t ao = (uint32_t)((wm + mt * 16 + a_row) * RSB
                                               + (kh + a_kof) * 2);
                ldsm4(ah[mt][0], ah[mt][1], ah[mt][2], ah[mt][3], tb + OFF_AH + ao);
                if (TERMS == 3)
                    ldsm4(al[mt][0], al[mt][1], al[mt][2], al[mt][3], tb + OFF_AL + ao);
            }
#pragma unroll
            for (int ng = 0; ng < 2; ++ng) {
                const uint32_t bo = (uint32_t)((wn + ng * 16 + b_row) * RSB
                                               + (kh + b_kof) * 2);
                ldsm4(bh[ng*2][0], bh[ng*2][1], bh[ng*2+1][0], bh[ng*2+1][1],
                      tb + OFF_BH + bo);
                ldsm4(bl[ng*2][0], bl[ng*2][1], bl[ng*2+1][0], bl[ng*2+1][1],
                      tb + OFF_BL + bo);
            }
#pragma unroll
            for (int mt = 0; mt < 2; ++mt)
#pragma unroll
                for (int nt = 0; nt < 4; ++nt) {
                    mma16816(c[mt][nt], ah[mt], bh[nt]);
                    mma16816h(cc[mt][nt], ah[mt], bl[nt]);
                    if (TERMS == 3) mma16816h(cc[mt][nt], al[mt], bh[nt]);
                }
        }
        __syncthreads();
    }

    // ---- epilogue ----
    const int mrow = lane >> 2;
    const int ncol = (lane & 3) * 2;
    const float* bias = (EPI == 3) ? pa.bias[bz] : nullptr;

#pragma unroll
    for (int mt = 0; mt < 2; ++mt)
#pragma unroll
        for (int nt = 0; nt < 4; ++nt) {
            __half2 p0 = *(__half2*)&cc[mt][nt][0];
            __half2 p1 = *(__half2*)&cc[mt][nt][1];
            float corr[4] = { __low2float(p0), __high2float(p0),
                              __low2float(p1), __high2float(p1) };
#pragma unroll
            for (int hf = 0; hf < 2; ++hf) {
                const int m = m0 + wm + mt * 16 + mrow + hf * 8;
                const int n = n0 + wn + nt * 8 + ncol;
                float v0 = c[mt][nt][hf * 2 + 0] + corr[hf * 2 + 0] * ILSCALE;
                float v1 = c[mt][nt][hf * 2 + 1] + corr[hf * 2 + 1] * ILSCALE;

                if (EPI == 0) {
                    float2 v; v.x = v0; v.y = v1;
                    *(float2*)&C0[bz * sC + (size_t)m * N + n] = v;
                } else {
                    v0 += bias[n]; v1 += bias[n + 1];
                    __half h0 = __float2half_rn(v0);
                    __half h1 = __float2half_rn(v1);
                    __half l0 = __float2half_rn((v0 - __half2float(h0)) * LSCALE);
                    __half l1 = __float2half_rn((v1 - __half2float(h1)) * LSCALE);
                    if (bz < 2) {
                        __half2 hh; hh.x = h0; hh.y = h1;
                        __half2 ll; ll.x = l0; ll.y = l1;
                        *(__half2*)&pa.oh[bz][(size_t)m * N + n] = hh;
                        *(__half2*)&pa.ol[bz][(size_t)m * N + n] = ll;
                    } else {
                        const int b = m >> 11;          // SEQ = 2048
                        const int s = m & 2047;
                        const size_t base = (size_t)b * DIM * SEQ + s;
                        pa.oh[2][base + (size_t)n * SEQ]       = h0;
                        pa.oh[2][base + (size_t)(n + 1) * SEQ] = h1;
                        pa.ol[2][base + (size_t)n * SEQ]       = l0;
                        pa.ol[2][base + (size_t)(n + 1) * SEQ] = l1;
                    }
                }
            }
        }
}

// ---------------------------------------------------------------------------
// fp32 -> fp16 hi + scaled-lo split (x)
// ---------------------------------------------------------------------------
__global__ __launch_bounds__(256)
void split_kernel(const float* __restrict__ in, __half* __restrict__ hi,
                  __half* __restrict__ lo, int n4)
{
    int i = blockIdx.x * 256 + threadIdx.x;
    if (i < n4) {
        float4 v = ((const float4*)in)[i];
        __half h[4], l[4];
        float vv[4] = {v.x, v.y, v.z, v.w};
#pragma unroll
        for (int j = 0; j < 4; ++j) {
            h[j] = __float2half_rn(vv[j]);
            l[j] = __float2half_rn((vv[j] - __half2float(h[j])) * LSCALE);
        }
        ((uint2*)hi)[i] = *(uint2*)h;
        ((uint2*)lo)[i] = *(uint2*)l;
    }
}

// fused W splits: z picks which weight matrix
__global__ __launch_bounds__(256)
void wsplit_kernel(const float* __restrict__ s0, const float* __restrict__ s1,
                   const float* __restrict__ s2,
                   __half* __restrict__ h0, __half* __restrict__ l0,
                   __half* __restrict__ h1, __half* __restrict__ l1,
                   __half* __restrict__ h2, __half* __restrict__ l2, int n4)
{
    const int z = blockIdx.z;
    const float* in = z == 0 ? s0 : z == 1 ? s1 : s2;
    __half* hi = z == 0 ? h0 : z == 1 ? h1 : h2;
    __half* lo = z == 0 ? l0 : z == 1 ? l1 : l2;
    int i = blockIdx.x * 256 + threadIdx.x;
    if (i < n4) {
        float4 v = ((const float4*)in)[i];
        __half h[4], l[4];
        float vv[4] = {v.x, v.y, v.z, v.w};
#pragma unroll
        for (int j = 0; j < 4; ++j) {
            h[j] = __float2half_rn(vv[j]);
            l[j] = __float2half_rn((vv[j] - __half2float(h[j])) * LSCALE);
        }
        ((uint2*)hi)[i] = *(uint2*)h;
        ((uint2*)lo)[i] = *(uint2*)l;
    }
}

// ---------------------------------------------------------------------------
// Row softmax over 2048, post-scale by norm, fp16 hi output only
// ---------------------------------------------------------------------------
__global__ __launch_bounds__(256)
void softmax_kernel(const float* __restrict__ S, __half* __restrict__ Ph,
                    float norm)
{
    const float* p = S + (long long)blockIdx.x * SEQ;
    __half* ph = Ph + (long long)blockIdx.x * SEQ;
    const int t = threadIdx.x;
    __shared__ float red[8];

    float v[8];
    float mx = -1e30f;
#pragma unroll
    for (int i = 0; i < 8; ++i) {
        v[i] = p[t + (i << 8)];
        mx = fmaxf(mx, v[i]);
    }
#pragma unroll
    for (int o = 16; o; o >>= 1) mx = fmaxf(mx, __shfl_xor_sync(0xffffffffu, mx, o));
    if ((t & 31) == 0) red[t >> 5] = mx;
    __syncthreads();
    mx = red[0];
#pragma unroll
    for (int i = 1; i < 8; ++i) mx = fmaxf(mx, red[i]);

    float s = 0.f;
#pragma unroll
    for (int i = 0; i < 8; ++i) { v[i] = __expf(v[i] - mx); s += v[i]; }
#pragma unroll
    for (int o = 16; o; o >>= 1) s += __shfl_xor_sync(0xffffffffu, s, o);
    __syncthreads();
    if ((t & 31) == 0) red[t >> 5] = s;
    __syncthreads();
    s = 0.f;
#pragma unroll
    for (int i = 0; i < 8; ++i) s += red[i];

    const float inv = norm / s;
#pragma unroll
    for (int i = 0; i < 8; ++i)
        ph[t + (i << 8)] = __float2half_rn(v[i] * inv);
}

// ---------------------------------------------------------------------------
extern "C" void kernel_launch(void* const* d_in, const int* in_sizes, int n_in,
                              void* d_out, int out_size)
{
    (void)in_sizes; (void)n_in; (void)out_size;
    const float* x  = (const float*)d_in[0];
    const float* Wq = (const float*)d_in[1];
    const float* bq = (const float*)d_in[2];
    const float* Wk = (const float*)d_in[3];
    const float* bk = (const float*)d_in[4];
    const float* Wv = (const float*)d_in[5];
    const float* bv = (const float*)d_in[6];
    float* out = (float*)d_out;

    __half *xh, *xl, *wqh, *wql, *wkh, *wkl, *wvh, *wvl;
    __half *Qh, *Ql, *Kh, *Kl, *Vth, *Vtl, *Ph;
    float *S;
    cudaGetSymbolAddress((void**)&xh,  g_xh);  cudaGetSymbolAddress((void**)&xl,  g_xl);
    cudaGetSymbolAddress((void**)&wqh, g_wqh); cudaGetSymbolAddress((void**)&wql, g_wql);
    cudaGetSymbolAddress((void**)&wkh, g_wkh); cudaGetSymbolAddress((void**)&wkl, g_wkl);
    cudaGetSymbolAddress((void**)&wvh, g_wvh); cudaGetSymbolAddress((void**)&wvl, g_wvl);
    cudaGetSymbolAddress((void**)&Qh,  g_Qh);  cudaGetSymbolAddress((void**)&Ql,  g_Ql);
    cudaGetSymbolAddress((void**)&Kh,  g_Kh);  cudaGetSymbolAddress((void**)&Kl,  g_Kl);
    cudaGetSymbolAddress((void**)&Vth, g_Vth); cudaGetSymbolAddress((void**)&Vtl, g_Vtl);
    cudaGetSymbolAddress((void**)&S,   g_S);
    cudaGetSymbolAddress((void**)&Ph,  g_Ph);

    cudaFuncSetAttribute(hgemm_kernel<0,3>, cudaFuncAttributeMaxDynamicSharedMemorySize, SMEM_REQ);
    cudaFuncSetAttribute(hgemm_kernel<0,2>, cudaFuncAttributeMaxDynamicSharedMemorySize, SMEM_REQ);
    cudaFuncSetAttribute(hgemm_kernel<3,3>, cudaFuncAttributeMaxDynamicSharedMemorySize, SMEM_REQ);

    const dim3 blk(256);
    const dim3 gblk(NTHR);
    ProjArgs pa;
    pa.bh[0] = wqh; pa.bh[1] = wkh; pa.bh[2] = wvh;
    pa.bl[0] = wql; pa.bl[1] = wkl; pa.bl[2] = wvl;
    pa.bias[0] = bq; pa.bias[1] = bk; pa.bias[2] = bv;
    pa.oh[0] = Qh; pa.oh[1] = Kh; pa.oh[2] = Vth;
    pa.ol[0] = Ql; pa.ol[1] = Kl; pa.ol[2] = Vtl;
    ProjArgs pz{};   // unused for non-projection GEMMs

    // 0: split x
    split_kernel<<<MTOT * DIM / 4 / 256, blk>>>(x, xh, xl, MTOT * DIM / 4);
    // 1: split all three weight matrices (fused via z)
    wsplit_kernel<<<dim3(DIM * DIM / 4 / 256, 1, 3), blk>>>(
        Wq, Wk, Wv, wqh, wql, wkh, wkl, wvh, wvl, DIM * DIM / 4);

    // 2: fused QKV projections: z in {Q, K, V}
    hgemm_kernel<3,3><<<dim3(DIM / BN, MTOT / BM, 3), gblk, SMEM_REQ>>>(
        xh, xl, nullptr, nullptr, nullptr, pa, DIM, DIM, 0, 0, 0);

    // 3: scores = Q @ K^T per batch
    hgemm_kernel<0,3><<<dim3(SEQ / BN, SEQ / BM, BATCH), gblk, SMEM_REQ>>>(
        Qh, Ql, Kh, Kl, S, pz, SEQ, DIM,
        (long long)SEQ * DIM, (long long)SEQ * DIM, (long long)SEQ * SEQ);

    // 4: softmax + post-scale 1/32
    softmax_kernel<<<BATCH * SEQ, blk>>>(S, Ph, 0.03125f);

    // 5: out = P @ Vt^T per batch (2-term: Ph·Vh + Ph·Vl)
    hgemm_kernel<0,2><<<dim3(DIM / BN, SEQ / BM, BATCH), gblk, SMEM_REQ>>>(
        Ph, nullptr, Vth, Vtl, out, pz, DIM, SEQ,
        (long long)SEQ * SEQ, (long long)DIM * SEQ, (long long)SEQ * DIM);
}

// round 12
// speedup vs baseline: 1.3686x; 1.1812x over previous
#include <cuda_runtime.h>
#include <cuda_fp16.h>
#include <cstdint>
#include <cstddef>

#define BATCH 4
#define SEQ   2048
#define DIM   1024
#define MTOT  (BATCH * SEQ)   // 8192

// lo-residual arrays are stored pre-scaled by LSCALE to keep fp16 products
// out of the subnormal range (f16-accumulator MMAs would flush them).
#define LSCALE 2048.0f
#define ILSCALE (1.0f / 2048.0f)

// ---- GEMM tiling ----
#define BM 128
#define BN 64
#define BK 32                 // 32 halves per row per tile
#define RSB 80                // smem row stride bytes (32*2 + 16 pad)
#define A_TILE (BM * RSB)     // 10240
#define B_TILE (BN * RSB)     // 5120
#define OFF_AH 0
#define OFF_AL (A_TILE)
#define OFF_BH (2 * A_TILE)
#define OFF_BL (2 * A_TILE + B_TILE)
#define STAGE (2 * A_TILE + 2 * B_TILE)  // 30720
#define NSTAGE 3
#define SMEM_REQ (NSTAGE * STAGE)        // 92160 -> 2 CTAs/SM fit in 228KB

#define NTHR 256              // 8 warps: 4x2 warp grid, 32x32 warp tile

// ---- device scratch ----
__device__ __half g_xh[(size_t)MTOT * DIM];
__device__ __half g_xl[(size_t)MTOT * DIM];
__device__ __half g_wqh[(size_t)DIM * DIM];
__device__ __half g_wql[(size_t)DIM * DIM];
__device__ __half g_wkh[(size_t)DIM * DIM];
__device__ __half g_wkl[(size_t)DIM * DIM];
__device__ __half g_wvh[(size_t)DIM * DIM];
__device__ __half g_wvl[(size_t)DIM * DIM];
__device__ __half g_Qh[(size_t)MTOT * DIM];
__device__ __half g_Ql[(size_t)MTOT * DIM];
__device__ __half g_Kh[(size_t)MTOT * DIM];
__device__ __half g_Kl[(size_t)MTOT * DIM];
__device__ __half g_Vth[(size_t)MTOT * DIM];   // [b][v][s] transposed V (hi only)
__device__ float  g_S [(size_t)BATCH * SEQ * SEQ];
__device__ __half g_Ph[(size_t)BATCH * SEQ * SEQ];

struct ProjArgs {
    const __half* bh[2];
    const __half* bl[2];
    const float*  bias[2];
    __half* oh[2];
    __half* ol[2];
};

// ---------------------------------------------------------------------------
__device__ __forceinline__ uint32_t cvta_smem(const void* p) {
    uint32_t r;
    asm("{ .reg .u64 t; cvta.to.shared.u64 t, %1; cvt.u32.u64 %0, t; }"
        : "=r"(r) : "l"(p));
    return r;
}
__device__ __forceinline__ void cpa16(uint32_t d, const void* s) {
    asm volatile("cp.async.cg.shared.global [%0], [%1], 16;" :: "r"(d), "l"(s));
}
__device__ __forceinline__ void cp_commit() {
    asm volatile("cp.async.commit_group;" ::: "memory");
}
__device__ __forceinline__ void ldsm4(uint32_t& r0, uint32_t& r1, uint32_t& r2,
                                      uint32_t& r3, uint32_t addr) {
    asm volatile("ldmatrix.sync.aligned.m8n8.x4.shared.b16 {%0,%1,%2,%3}, [%4];"
                 : "=r"(r0), "=r"(r1), "=r"(r2), "=r"(r3) : "r"(addr));
}
// main term: fp32 accumulate
__device__ __forceinline__ void mma16816(float* c, const uint32_t* a,
                                         const uint32_t* b) {
    asm volatile(
        "mma.sync.aligned.m16n8k16.row.col.f32.f16.f16.f32 "
        "{%0,%1,%2,%3}, {%4,%5,%6,%7}, {%8,%9}, {%0,%1,%2,%3};"
        : "+f"(c[0]), "+f"(c[1]), "+f"(c[2]), "+f"(c[3])
        : "r"(a[0]), "r"(a[1]), "r"(a[2]), "r"(a[3]), "r"(b[0]), "r"(b[1]));
}
// correction terms: fp16 accumulate (values are small, pre-scaled by LSCALE)
__device__ __forceinline__ void mma16816h(uint32_t* c, const uint32_t* a,
                                          const uint32_t* b) {
    asm volatile(
        "mma.sync.aligned.m16n8k16.row.col.f16.f16.f16.f16 "
        "{%0,%1}, {%2,%3,%4,%5}, {%6,%7}, {%0,%1};"
        : "+r"(c[0]), "+r"(c[1])
        : "r"(a[0]), "r"(a[1]), "r"(a[2]), "r"(a[3]), "r"(b[0]), "r"(b[1]));
}

// ---------------------------------------------------------------------------
// Split-fp16 GEMM:  C = A @ B^T  (A:[M,K], B:[N,K], K-major), main fp32-accum
// + optional fp16-accum corrections (lo arrays pre-scaled by LSCALE).
// 128x64 CTA tile, 256 threads, 8 warps (4x2), 32x32 warp tile, 2 CTAs/SM.
// Single __syncthreads per k-iteration (wait -> sync -> issue loads -> compute).
// EPI 0: plain fp32 out
// EPI 3: row-major split hi/lo out (+bias), blockIdx.z picks W/bias/out (Q,K)
// EPI 4: transposed hi-only out (+bias) — V projection writes Vt[b][n][s]
// TERMS 1: Ah·Bh ; 2: +Ah·Bl ; 3: +Al·Bh
// ---------------------------------------------------------------------------
template <int EPI, int TERMS>
__global__ __launch_bounds__(NTHR, 2)
void hgemm_kernel(const __half* __restrict__ Ahg, const __half* __restrict__ Alg,
                  const __half* __restrict__ Bhg, const __half* __restrict__ Blg,
                  float* __restrict__ C0, ProjArgs pa,
                  int N, int K,
                  long long sA, long long sB, long long sC)
{
    extern __shared__ char smem_raw[];
    const uint32_t sb = cvta_smem(smem_raw);

    const int tid  = threadIdx.x;
    const int wid  = tid >> 5;
    const int lane = tid & 31;
    const long long bz = blockIdx.z;

    const __half* Bh_;
    const __half* Bl_;
    if (EPI >= 3) { Bh_ = pa.bh[bz]; Bl_ = pa.bl[bz]; }
    else          { Bh_ = Bhg + bz * sB; Bl_ = (TERMS >= 2) ? Blg + bz * sB : nullptr; }
    const __half* Ah_ = Ahg + (EPI >= 3 ? 0 : bz * sA);
    const __half* Al_ = (TERMS == 3) ? (Alg + (EPI >= 3 ? 0 : bz * sA)) : nullptr;

    const int m0 = blockIdx.y * BM;
    const int n0 = blockIdx.x * BN;

    const int wm = (wid & 3) * 32;   // warp row offset (4 warps in m)
    const int wn = (wid >> 2) * 32;  // warp col offset (2 warps in n)

    float c[2][4][4];
    uint32_t cc[2][4][2];            // f16x2 correction accumulators
#pragma unroll
    for (int mt = 0; mt < 2; ++mt)
#pragma unroll
        for (int nt = 0; nt < 4; ++nt) {
#pragma unroll
            for (int i = 0; i < 4; ++i) c[mt][nt][i] = 0.f;
            cc[mt][nt][0] = 0u; cc[mt][nt][1] = 0u;
        }

    const int NK = K / BK;

    // loader: A tile = 512 16B chunks (2 rounds of 256), B tile = 256 chunks
    const int arow = tid >> 2;            // A round r: row = arow + r*64
    const int akcc = (tid & 3) * 8;
    const uint32_t aso = (uint32_t)(arow * RSB + akcc * 2);

    auto load_stage = [&](int slot, int kc) {
        const uint32_t tb = sb + slot * STAGE;
#pragma unroll
        for (int r = 0; r < 2; ++r) {
            const long long ga = (long long)(m0 + arow + r * 64) * K + kc + akcc;
            const uint32_t so = aso + (uint32_t)(r * 64 * RSB);
            cpa16(tb + OFF_AH + so, Ah_ + ga);
            if (TERMS == 3) cpa16(tb + OFF_AL + so, Al_ + ga);
        }
        const long long gb = (long long)(n0 + arow) * K + kc + akcc;
        cpa16(tb + OFF_BH + aso, Bh_ + gb);
        if (TERMS >= 2) cpa16(tb + OFF_BL + aso, Bl_ + gb);
    };

    // prefetch NSTAGE-1 stages
#pragma unroll
    for (int s = 0; s < NSTAGE - 1; ++s) { load_stage(s, s * BK); cp_commit(); }

    const int a_row = (lane & 15);
    const int a_kof = (lane >> 4) * 8;
    const int b_row = ((lane >> 4) << 3) + (lane & 7);
    const int b_kof = ((lane >> 3) & 1) * 8;

    for (int it = 0; it < NK; ++it) {
        // stage `it` (group #it) complete: allow only the newest group pending
        if (it < NK - 1)
            asm volatile("cp.async.wait_group 1;" ::: "memory");
        else
            asm volatile("cp.async.wait_group 0;" ::: "memory");
        __syncthreads();
        // refill slot (it+2)%3 — its last readers ran in iter it-1, before the
        // barrier above, so the async writes below cannot race them.
        if (it + NSTAGE - 1 < NK) {
            load_stage((it + NSTAGE - 1) % NSTAGE, (it + NSTAGE - 1) * BK);
            cp_commit();
        }

        const uint32_t tb = sb + (it % NSTAGE) * STAGE;
#pragma unroll
        for (int ks = 0; ks < 2; ++ks) {
            const int kh = ks * 16;
            uint32_t ah[2][4], al[2][4], bh[4][2], bl[4][2];
#pragma unroll
            for (int mt = 0; mt < 2; ++mt) {
                const uint32_t ao = (uint32_t)((wm + mt * 16 + a_row) * RSB
                                               + (kh + a_kof) * 2);
                ldsm4(ah[mt][0], ah[mt][1], ah[mt][2], ah[mt][3], tb + OFF_AH + ao);
                if (TERMS == 3)
                    ldsm4(al[mt][0], al[mt][1], al[mt][2], al[mt][3], tb + OFF_AL + ao);
            }
#pragma unroll
            for (int ng = 0; ng < 2; ++ng) {
                const uint32_t bo = (uint32_t)((wn + ng * 16 + b_row) * RSB
                                               + (kh + b_kof) * 2);
                ldsm4(bh[ng*2][0], bh[ng*2][1], bh[ng*2+1][0], bh[ng*2+1][1],
                      tb + OFF_BH + bo);
                if (TERMS >= 2)
                    ldsm4(bl[ng*2][0], bl[ng*2][1], bl[ng*2+1][0], bl[ng*2+1][1],
                          tb + OFF_BL + bo);
            }
#pragma unroll
            for (int mt = 0; mt < 2; ++mt)
#pragma unroll
                for (int nt = 0; nt < 4; ++nt) {
                    mma16816(c[mt][nt], ah[mt], bh[nt]);
                    if (TERMS >= 2) mma16816h(cc[mt][nt], ah[mt], bl[nt]);
                    if (TERMS == 3) mma16816h(cc[mt][nt], al[mt], bh[nt]);
                }
        }
    }
    __syncthreads();   // protect smem before CTA exit / epilogue reuse

    // ---- epilogue ----
    const int mrow = lane >> 2;
    const int ncol = (lane & 3) * 2;
    const float* bias = (EPI >= 3) ? pa.bias[bz] : nullptr;

#pragma unroll
    for (int mt = 0; mt < 2; ++mt)
#pragma unroll
        for (int nt = 0; nt < 4; ++nt) {
            float corr[4] = {0.f, 0.f, 0.f, 0.f};
            if (TERMS >= 2) {
                __half2 p0 = *(__half2*)&cc[mt][nt][0];
                __half2 p1 = *(__half2*)&cc[mt][nt][1];
                corr[0] = __low2float(p0);  corr[1] = __high2float(p0);
                corr[2] = __low2float(p1);  corr[3] = __high2float(p1);
            }
#pragma unroll
            for (int hf = 0; hf < 2; ++hf) {
                const int m = m0 + wm + mt * 16 + mrow + hf * 8;
                const int n = n0 + wn + nt * 8 + ncol;
                float v0 = c[mt][nt][hf * 2 + 0] + corr[hf * 2 + 0] * ILSCALE;
                float v1 = c[mt][nt][hf * 2 + 1] + corr[hf * 2 + 1] * ILSCALE;

                if (EPI == 0) {
                    float2 v; v.x = v0; v.y = v1;
                    *(float2*)&C0[bz * sC + (size_t)m * N + n] = v;
                } else if (EPI == 3) {
                    v0 += bias[n]; v1 += bias[n + 1];
                    __half h0 = __float2half_rn(v0);
                    __half h1 = __float2half_rn(v1);
                    __half l0 = __float2half_rn((v0 - __half2float(h0)) * LSCALE);
                    __half l1 = __float2half_rn((v1 - __half2float(h1)) * LSCALE);
                    __half2 hh; hh.x = h0; hh.y = h1;
                    __half2 ll; ll.x = l0; ll.y = l1;
                    *(__half2*)&pa.oh[bz][(size_t)m * N + n] = hh;
                    *(__half2*)&pa.ol[bz][(size_t)m * N + n] = ll;
                } else {   // EPI == 4: transposed hi-only (V)
                    v0 += bias[n]; v1 += bias[n + 1];
                    const int b = m >> 11;          // SEQ = 2048
                    const int s = m & 2047;
                    const size_t base = (size_t)b * DIM * SEQ + s;
                    pa.oh[0][base + (size_t)n * SEQ]       = __float2half_rn(v0);
                    pa.oh[0][base + (size_t)(n + 1) * SEQ] = __float2half_rn(v1);
                }
            }
        }
}

// ---------------------------------------------------------------------------
// fp32 -> fp16 hi + scaled-lo split (x)
// ---------------------------------------------------------------------------
__global__ __launch_bounds__(256)
void split_kernel(const float* __restrict__ in, __half* __restrict__ hi,
                  __half* __restrict__ lo, int n4)
{
    int i = blockIdx.x * 256 + threadIdx.x;
    if (i < n4) {
        float4 v = ((const float4*)in)[i];
        __half h[4], l[4];
        float vv[4] = {v.x, v.y, v.z, v.w};
#pragma unroll
        for (int j = 0; j < 4; ++j) {
            h[j] = __float2half_rn(vv[j]);
            l[j] = __float2half_rn((vv[j] - __half2float(h[j])) * LSCALE);
        }
        ((uint2*)hi)[i] = *(uint2*)h;
        ((uint2*)lo)[i] = *(uint2*)l;
    }
}

// fused W splits: z picks which weight matrix
__global__ __launch_bounds__(256)
void wsplit_kernel(const float* __restrict__ s0, const float* __restrict__ s1,
                   const float* __restrict__ s2,
                   __half* __restrict__ h0, __half* __restrict__ l0,
                   __half* __restrict__ h1, __half* __restrict__ l1,
                   __half* __restrict__ h2, __half* __restrict__ l2, int n4)
{
    const int z = blockIdx.z;
    const float* in = z == 0 ? s0 : z == 1 ? s1 : s2;
    __half* hi = z == 0 ? h0 : z == 1 ? h1 : h2;
    __half* lo = z == 0 ? l0 : z == 1 ? l1 : l2;
    int i = blockIdx.x * 256 + threadIdx.x;
    if (i < n4) {
        float4 v = ((const float4*)in)[i];
        __half h[4], l[4];
        float vv[4] = {v.x, v.y, v.z, v.w};
#pragma unroll
        for (int j = 0; j < 4; ++j) {
            h[j] = __float2half_rn(vv[j]);
            l[j] = __float2half_rn((vv[j] - __half2float(h[j])) * LSCALE);
        }
        ((uint2*)hi)[i] = *(uint2*)h;
        ((uint2*)lo)[i] = *(uint2*)l;
    }
}

// ---------------------------------------------------------------------------
// Row softmax over 2048, post-scale by norm, fp16 hi output only
// ---------------------------------------------------------------------------
__global__ __launch_bounds__(256)
void softmax_kernel(const float* __restrict__ S, __half* __restrict__ Ph,
                    float norm)
{
    const float* p = S + (long long)blockIdx.x * SEQ;
    __half* ph = Ph + (long long)blockIdx.x * SEQ;
    const int t = threadIdx.x;
    __shared__ float red[8];

    float v[8];
    float mx = -1e30f;
#pragma unroll
    for (int i = 0; i < 8; ++i) {
        v[i] = p[t + (i << 8)];
        mx = fmaxf(mx, v[i]);
    }
#pragma unroll
    for (int o = 16; o; o >>= 1) mx = fmaxf(mx, __shfl_xor_sync(0xffffffffu, mx, o));
    if ((t & 31) == 0) red[t >> 5] = mx;
    __syncthreads();
    mx = red[0];
#pragma unroll
    for (int i = 1; i < 8; ++i) mx = fmaxf(mx, red[i]);

    float s = 0.f;
#pragma unroll
    for (int i = 0; i < 8; ++i) { v[i] = __expf(v[i] - mx); s += v[i]; }
#pragma unroll
    for (int o = 16; o; o >>= 1) s += __shfl_xor_sync(0xffffffffu, s, o);
    __syncthreads();
    if ((t & 31) == 0) red[t >> 5] = s;
    __syncthreads();
    s = 0.f;
#pragma unroll
    for (int i = 0; i < 8; ++i) s += red[i];

    const float inv = norm / s;
#pragma unroll
    for (int i = 0; i < 8; ++i)
        ph[t + (i << 8)] = __float2half_rn(v[i] * inv);
}

// ---------------------------------------------------------------------------
extern "C" void kernel_launch(void* const* d_in, const int* in_sizes, int n_in,
                              void* d_out, int out_size)
{
    (void)in_sizes; (void)n_in; (void)out_size;
    const float* x  = (const float*)d_in[0];
    const float* Wq = (const float*)d_in[1];
    const float* bq = (const float*)d_in[2];
    const float* Wk = (const float*)d_in[3];
    const float* bk = (const float*)d_in[4];
    const float* Wv = (const float*)d_in[5];
    const float* bv = (const float*)d_in[6];
    float* out = (float*)d_out;

    __half *xh, *xl, *wqh, *wql, *wkh, *wkl, *wvh, *wvl;
    __half *Qh, *Ql, *Kh, *Kl, *Vth, *Ph;
    float *S;
    cudaGetSymbolAddress((void**)&xh,  g_xh);  cudaGetSymbolAddress((void**)&xl,  g_xl);
    cudaGetSymbolAddress((void**)&wqh, g_wqh); cudaGetSymbolAddress((void**)&wql, g_wql);
    cudaGetSymbolAddress((void**)&wkh, g_wkh); cudaGetSymbolAddress((void**)&wkl, g_wkl);
    cudaGetSymbolAddress((void**)&wvh, g_wvh); cudaGetSymbolAddress((void**)&wvl, g_wvl);
    cudaGetSymbolAddress((void**)&Qh,  g_Qh);  cudaGetSymbolAddress((void**)&Ql,  g_Ql);
    cudaGetSymbolAddress((void**)&Kh,  g_Kh);  cudaGetSymbolAddress((void**)&Kl,  g_Kl);
    cudaGetSymbolAddress((void**)&Vth, g_Vth);
    cudaGetSymbolAddress((void**)&S,   g_S);
    cudaGetSymbolAddress((void**)&Ph,  g_Ph);

    cudaFuncSetAttribute(hgemm_kernel<0,3>, cudaFuncAttributeMaxDynamicSharedMemorySize, SMEM_REQ);
    cudaFuncSetAttribute(hgemm_kernel<0,1>, cudaFuncAttributeMaxDynamicSharedMemorySize, SMEM_REQ);
    cudaFuncSetAttribute(hgemm_kernel<3,3>, cudaFuncAttributeMaxDynamicSharedMemorySize, SMEM_REQ);
    cudaFuncSetAttribute(hgemm_kernel<4,2>, cudaFuncAttributeMaxDynamicSharedMemorySize, SMEM_REQ);

    const dim3 blk(256);
    const dim3 gblk(NTHR);

    ProjArgs pqk;   // Q (z=0), K (z=1)
    pqk.bh[0] = wqh; pqk.bh[1] = wkh;
    pqk.bl[0] = wql; pqk.bl[1] = wkl;
    pqk.bias[0] = bq; pqk.bias[1] = bk;
    pqk.oh[0] = Qh; pqk.oh[1] = Kh;
    pqk.ol[0] = Ql; pqk.ol[1] = Kl;

    ProjArgs pv{};  // V (z=0)
    pv.bh[0] = wvh; pv.bl[0] = wvl; pv.bias[0] = bv; pv.oh[0] = Vth;

    ProjArgs pz{};  // unused for non-projection GEMMs

    // 0: split x
    split_kernel<<<MTOT * DIM / 4 / 256, blk>>>(x, xh, xl, MTOT * DIM / 4);
    // 1: split all three weight matrices (fused via z)
    wsplit_kernel<<<dim3(DIM * DIM / 4 / 256, 1, 3), blk>>>(
        Wq, Wk, Wv, wqh, wql, wkh, wkl, wvh, wvl, DIM * DIM / 4);

    // 2: Q,K projections (3-term, split output)
    hgemm_kernel<3,3><<<dim3(DIM / BN, MTOT / BM, 2), gblk, SMEM_REQ>>>(
        xh, xl, nullptr, nullptr, nullptr, pqk, DIM, DIM, 0, 0, 0);

    // 3: V projection (2-term, transposed hi-only output)
    hgemm_kernel<4,2><<<dim3(DIM / BN, MTOT / BM, 1), gblk, SMEM_REQ>>>(
        xh, nullptr, nullptr, nullptr, nullptr, pv, DIM, DIM, 0, 0, 0);

    // 4: scores = Q @ K^T per batch (3-term)
    hgemm_kernel<0,3><<<dim3(SEQ / BN, SEQ / BM, BATCH), gblk, SMEM_REQ>>>(
        Qh, Ql, Kh, Kl, S, pz, SEQ, DIM,
        (long long)SEQ * DIM, (long long)SEQ * DIM, (long long)SEQ * SEQ);

    // 5: softmax + post-scale 1/32
    softmax_kernel<<<BATCH * SEQ, blk>>>(S, Ph, 0.03125f);

    // 6: out = Ph @ Vth^T per batch (1-term)
    hgemm_kernel<0,1><<<dim3(DIM / BN, SEQ / BM, BATCH), gblk, SMEM_REQ>>>(
        Ph, nullptr, Vth, nullptr, out, pz, DIM, SEQ,
        (long long)SEQ * SEQ, (long long)DIM * SEQ, (long long)SEQ * DIM);
}